// round 16
// baseline (speedup 1.0000x reference)
#include <cuda_runtime.h>
#include <cuda_fp16.h>
#include <math.h>

#define HID   128
#define HEADS 4
#define HDIM  32
#define NMAX  50176
#define EMAX  800000
#define SCANB 512

// ---------------- scratch ---------------------------------------------------
__device__ __half g_hc[NMAX * HID];      // h_combined fp16
__device__ __half g_qh[NMAX * HID];
__device__ __half g_kh[NMAX * HID];
__device__ __half g_vh[NMAX * HID];
__device__ __half g_wqh[HID * HID];      // fp16 weights
__device__ __half g_wkh[HID * HID];
__device__ __half g_wvh[HID * HID];
__device__ __half g_woh[HID * HID];
__device__ float  g_agg[NMAX * HID];     // unnormalized sum of w*v (fp32 atomics)
__device__ float  g_expsum[NMAX * HEADS];
__device__ int    g_cnt[NMAX];
__device__ int    g_cur[NMAX];
__device__ int    g_chunksum[256];
__device__ int4   g_adjr[EMAX];          // CSR records: (row, col, gate*scale bits, 0)

// ---------------- helpers ----------------------------------------------------
__device__ __forceinline__ unsigned smem_u32(const void* p) {
    return (unsigned)__cvta_generic_to_shared(p);
}
__device__ __forceinline__ void cp16(unsigned dst, const void* src) {
    asm volatile("cp.async.cg.shared.global [%0], [%1], 16;" :: "r"(dst), "l"(src));
}
__device__ __forceinline__ void cp_commit_wait() {
    asm volatile("cp.async.commit_group;");
    asm volatile("cp.async.wait_group 0;" ::: "memory");
}
__device__ __forceinline__ void ldsm_x4(unsigned& r0, unsigned& r1,
                                        unsigned& r2, unsigned& r3, unsigned a) {
    asm volatile("ldmatrix.sync.aligned.m8n8.x4.shared.b16 {%0,%1,%2,%3},[%4];"
                 : "=r"(r0), "=r"(r1), "=r"(r2), "=r"(r3) : "r"(a));
}
__device__ __forceinline__ void mma16816(float* c, const unsigned* a, const unsigned* b) {
    asm volatile(
        "mma.sync.aligned.m16n8k16.row.col.f32.f16.f16.f32 "
        "{%0,%1,%2,%3},{%4,%5,%6,%7},{%8,%9},{%0,%1,%2,%3};"
        : "+f"(c[0]), "+f"(c[1]), "+f"(c[2]), "+f"(c[3])
        : "r"(a[0]), "r"(a[1]), "r"(a[2]), "r"(a[3]), "r"(b[0]), "r"(b[1]));
}

#define AK 72   // padded K stride (halves) for smem tiles

// ---------------- zero degree counts -----------------------------------------
__global__ void zero_cnt(int n) {
    int i = blockIdx.x * blockDim.x + threadIdx.x;
    if (i < n) g_cnt[i] = 0;
}

// ---------------- prep: convert weights to fp16 ------------------------------
__global__ void prep_weights(const float* __restrict__ Wq,
                             const float* __restrict__ Wk,
                             const float* __restrict__ Wv,
                             const float* __restrict__ Wo) {
    int i = blockIdx.x * blockDim.x + threadIdx.x;
    if (i >= 4 * HID * HID / 4) return;
    int which = i / (HID * HID / 4);
    int off = (i % (HID * HID / 4)) * 4;
    const float* src = (which == 0) ? Wq : (which == 1) ? Wk : (which == 2) ? Wv : Wo;
    __half* dst = (which == 0) ? g_wqh : (which == 1) ? g_wkh : (which == 2) ? g_wvh : g_woh;
    float4 v = *(const float4*)&src[off];
    __half2* d = (__half2*)&dst[off];
    d[0] = __floats2half2_rn(v.x, v.y);
    d[1] = __floats2half2_rn(v.z, v.w);
}

// ---------------- prep: h_combined -> fp16, zero agg/expsum ------------------
__global__ void prep_hc(const float* __restrict__ h,
                        const float* __restrict__ frac,
                        const float* __restrict__ We,
                        const float* __restrict__ be,
                        int n) {
    int idx = blockIdx.x * blockDim.x + threadIdx.x;
    if (idx >= n * 32) return;
    int m = idx >> 5;
    int k4 = (idx & 31) * 4;
    float4 hv = *(const float4*)&h[m * HID + k4];
    float f0 = __ldg(&frac[m * 3 + 0]);
    float f1 = __ldg(&frac[m * 3 + 1]);
    float f2 = __ldg(&frac[m * 3 + 2]);
    float x[4] = {hv.x, hv.y, hv.z, hv.w};
#pragma unroll
    for (int u = 0; u < 4; u++) {
        int kc = k4 + u;
        x[u] += f0 * __ldg(&We[kc * 3 + 0]) + f1 * __ldg(&We[kc * 3 + 1])
              + f2 * __ldg(&We[kc * 3 + 2]) + __ldg(&be[kc]);
    }
    __half2* d = (__half2*)&g_hc[m * HID + k4];
    d[0] = __floats2half2_rn(x[0], x[1]);
    d[1] = __floats2half2_rn(x[2], x[3]);
    *(float4*)&g_agg[idx * 4] = make_float4(0.f, 0.f, 0.f, 0.f);
    if (idx < n * HEADS) g_expsum[idx] = 0.f;
}

// ---------------- degree histogram -------------------------------------------
__global__ void hist_kernel(const int* __restrict__ ei, int E) {
    int e = blockIdx.x * blockDim.x + threadIdx.x;
    if (e < E) atomicAdd(&g_cnt[ei[e]], 1);
}

// ---------------- 3-phase exclusive scan of g_cnt -> g_cur -------------------
__global__ void scan_phase1(int n) {
    int i = blockIdx.x * SCANB + threadIdx.x;
    int c = (i < n) ? g_cnt[i] : 0;
    for (int o = 16; o; o >>= 1) c += __shfl_down_sync(0xFFFFFFFFu, c, o);
    __shared__ int ws[16];
    if ((threadIdx.x & 31) == 0) ws[threadIdx.x >> 5] = c;
    __syncthreads();
    if (threadIdx.x < 16) {
        int v = ws[threadIdx.x];
        for (int o = 8; o; o >>= 1) v += __shfl_down_sync(0xFFFFu, v, o);
        if (threadIdx.x == 0) g_chunksum[blockIdx.x] = v;
    }
}
__global__ void scan_phase2(int nch) {
    if (threadIdx.x == 0) {
        int run = 0;
        for (int j = 0; j < nch; j++) {
            int t = g_chunksum[j];
            g_chunksum[j] = run;
            run += t;
        }
    }
}
__global__ void scan_phase3(int n) {
    int i = blockIdx.x * SCANB + threadIdx.x;
    int c = (i < n) ? g_cnt[i] : 0;
    int lane = threadIdx.x & 31, w = threadIdx.x >> 5;
    int v = c;
    for (int o = 1; o < 32; o <<= 1) {
        int t = __shfl_up_sync(0xFFFFFFFFu, v, o);
        if (lane >= o) v += t;
    }
    __shared__ int ws[16];
    if (lane == 31) ws[w] = v;
    __syncthreads();
    if (threadIdx.x < 16) {
        int s = ws[threadIdx.x];
        for (int o = 1; o < 16; o <<= 1) {
            int t = __shfl_up_sync(0xFFFFu, s, o);
            if ((int)threadIdx.x >= o) s += t;
        }
        ws[threadIdx.x] = s;
    }
    __syncthreads();
    int base = g_chunksum[blockIdx.x] + (w ? ws[w - 1] : 0);
    if (i < n) g_cur[i] = base + v - c;
}

// ---------------- scatter + fused gate MLP (warp per edge) -------------------
__global__ void scatter_gate(const int* __restrict__ ei,
                             const float* __restrict__ dist,
                             const float* __restrict__ Wg1, const float* __restrict__ bg1,
                             const float* __restrict__ Wg2, const float* __restrict__ bg2,
                             int E) {
    int warp = (blockIdx.x * blockDim.x + threadIdx.x) >> 5;
    int lane = threadIdx.x & 31;
    if (warp >= E) return;

    float d = dist[warp];
    float t = fmaf(d, Wg1[lane], bg1[lane]);
    float hsi = t / (1.f + __expf(-t));
    float gp = hsi * Wg2[lane];
    gp += __shfl_xor_sync(0xFFFFFFFFu, gp, 16);
    gp += __shfl_xor_sync(0xFFFFFFFFu, gp, 8);
    gp += __shfl_xor_sync(0xFFFFFFFFu, gp, 4);
    gp += __shfl_xor_sync(0xFFFFFFFFu, gp, 2);
    gp += __shfl_xor_sync(0xFFFFFFFFu, gp, 1);

    if (lane == 0) {
        float g = 1.f / (1.f + __expf(-(gp + bg2[0])));
        int row = ei[warp];
        int pos = atomicAdd(&g_cur[row], 1);
        g_adjr[pos] = make_int4(row, ei[E + warp],
                                __float_as_int(g * 0.17677669529663687f), 0);
    }
}

// ---------------- QKV projections: pure fp16 GEMM w/ cp.async tiles ----------
__global__ void __launch_bounds__(256, 2)
qkv_gemm(const float* __restrict__ bq,
         const float* __restrict__ bk,
         const float* __restrict__ bv,
         int n) {
    __shared__ __align__(16) __half As[128][AK];
    __shared__ __align__(16) __half Bs[128][AK];

    int m0 = blockIdx.x * 128;
    const __half* W; const float* bias; __half* outbuf;
    if (blockIdx.y == 0)      { W = g_wqh; bias = bq; outbuf = g_qh; }
    else if (blockIdx.y == 1) { W = g_wkh; bias = bk; outbuf = g_kh; }
    else                      { W = g_wvh; bias = bv; outbuf = g_vh; }

    int tid = threadIdx.x;
    int wid = tid >> 5, lane = tid & 31;
    int wm = (wid & 3) * 32;
    int wn = (wid >> 2) * 64;

    float acc[2][8][4];
#pragma unroll
    for (int i = 0; i < 2; i++)
#pragma unroll
        for (int j = 0; j < 8; j++)
#pragma unroll
            for (int t = 0; t < 4; t++) acc[i][j][t] = 0.f;

    for (int k0 = 0; k0 < HID; k0 += 64) {
        for (int idx = tid; idx < 1024; idx += 256) {
            int r = idx >> 3;
            int c16 = idx & 7;
            cp16(smem_u32(&As[r][c16 * 8]), &g_hc[(m0 + r) * HID + k0 + c16 * 8]);
        }
        for (int idx = tid; idx < 1024; idx += 256) {
            int c = idx >> 3;
            int c16 = idx & 7;
            cp16(smem_u32(&Bs[c][c16 * 8]), &W[c * HID + k0 + c16 * 8]);
        }
        cp_commit_wait();
        __syncthreads();

#pragma unroll
        for (int ks = 0; ks < 64; ks += 16) {
            unsigned af[2][4];
#pragma unroll
            for (int mf = 0; mf < 2; mf++) {
                unsigned a = smem_u32(&As[wm + mf * 16 + (lane & 15)][ks + (lane >> 4) * 8]);
                ldsm_x4(af[mf][0], af[mf][1], af[mf][2], af[mf][3], a);
            }
            unsigned bf[8][2];
#pragma unroll
            for (int ng = 0; ng < 4; ng++) {
                unsigned a = smem_u32(&Bs[wn + ng * 16 + (lane & 15)][ks + (lane >> 4) * 8]);
                unsigned r0, r1, r2, r3;
                ldsm_x4(r0, r1, r2, r3, a);
                bf[ng * 2][0] = r0; bf[ng * 2][1] = r2;
                bf[ng * 2 + 1][0] = r1; bf[ng * 2 + 1][1] = r3;
            }
#pragma unroll
            for (int mf = 0; mf < 2; mf++)
#pragma unroll
                for (int nf = 0; nf < 8; nf++)
                    mma16816(acc[mf][nf], af[mf], bf[nf]);
        }
        __syncthreads();
    }

#pragma unroll
    for (int mf = 0; mf < 2; mf++) {
        int r0 = m0 + wm + mf * 16 + (lane >> 2);
#pragma unroll
        for (int nf = 0; nf < 8; nf++) {
            int c = wn + nf * 8 + (lane & 3) * 2;
            float b0 = bias[c], b1 = bias[c + 1];
            if (r0 < n)
                *(__half2*)&outbuf[r0 * HID + c] =
                    __floats2half2_rn(acc[mf][nf][0] + b0, acc[mf][nf][1] + b1);
            if (r0 + 8 < n)
                *(__half2*)&outbuf[(r0 + 8) * HID + c] =
                    __floats2half2_rn(acc[mf][nf][2] + b0, acc[mf][nf][3] + b1);
        }
    }
}

// ---------------- segmented push over CSR ------------------------------------
// warp owns 8 consecutive CSR slots; each 16-lane half owns 4 contiguous slots.
// Same-row edges accumulate in registers; atomics fire only on row change.
__global__ void __launch_bounds__(256)
edge_csr(int E) {
    int warp = (blockIdx.x * blockDim.x + threadIdx.x) >> 5;
    int lane = threadIdx.x & 31;
    int base = warp * 8;
    if (base >= E) return;
    int half = lane >> 4;
    int sub  = lane & 15;

    // lanes 0..7 load the warp's 8 records; broadcast via shfl
    int4 rec = make_int4(-1, 0, 0, 0);
    if (lane < 8 && base + lane < E) rec = g_adjr[base + lane];

    float2 q[4];
    float2 a2[4];
#pragma unroll
    for (int u = 0; u < 4; u++) a2[u] = make_float2(0.f, 0.f);
    float es = 0.f;
    int curRow = -1;

#pragma unroll
    for (int it = 0; it < 4; it++) {
        int slot = half * 4 + it;      // uniform per half-warp
        int row = __shfl_sync(0xFFFFFFFFu, rec.x, slot);
        int col = __shfl_sync(0xFFFFFFFFu, rec.y, slot);
        float gt = __int_as_float(__shfl_sync(0xFFFFFFFFu, rec.z, slot));

        if (row != curRow) {
            if (curRow >= 0) {
                float* dst = &g_agg[curRow * HID + sub * 8];
                asm volatile("red.global.add.v4.f32 [%0], {%1,%2,%3,%4};"
                             :: "l"(dst), "f"(a2[0].x), "f"(a2[0].y),
                                "f"(a2[1].x), "f"(a2[1].y));
                asm volatile("red.global.add.v4.f32 [%0], {%1,%2,%3,%4};"
                             :: "l"(dst + 4), "f"(a2[2].x), "f"(a2[2].y),
                                "f"(a2[3].x), "f"(a2[3].y));
                if ((sub & 3) == 0)
                    atomicAdd(&g_expsum[curRow * HEADS + (sub >> 2)], es);
#pragma unroll
                for (int u = 0; u < 4; u++) a2[u] = make_float2(0.f, 0.f);
                es = 0.f;
            }
            curRow = row;
            if (row >= 0) {
                union { float4 f; __half2 h[4]; } q4;
                q4.f = *(const float4*)&g_qh[row * HID + sub * 8];
#pragma unroll
                for (int u = 0; u < 4; u++) q[u] = __half22float2(q4.h[u]);
            }
        }
        if (row >= 0) {
            union { float4 f; __half2 h[4]; } k4, v4;
            k4.f = *(const float4*)&g_kh[col * HID + sub * 8];
            v4.f = *(const float4*)&g_vh[col * HID + sub * 8];

            float p = 0.f;
#pragma unroll
            for (int u = 0; u < 4; u++) {
                float2 kk = __half22float2(k4.h[u]);
                p += q[u].x * kk.x + q[u].y * kk.y;
            }
            // reduce over the 4 lanes of this head group (head = sub>>2)
            p += __shfl_xor_sync(0xFFFFFFFFu, p, 1);
            p += __shfl_xor_sync(0xFFFFFFFFu, p, 2);

            float w = __expf(p * gt);
#pragma unroll
            for (int u = 0; u < 4; u++) {
                float2 vv = __half22float2(v4.h[u]);
                a2[u].x += w * vv.x;
                a2[u].y += w * vv.y;
            }
            es += w;
        }
    }

    if (curRow >= 0) {
        float* dst = &g_agg[curRow * HID + sub * 8];
        asm volatile("red.global.add.v4.f32 [%0], {%1,%2,%3,%4};"
                     :: "l"(dst), "f"(a2[0].x), "f"(a2[0].y),
                        "f"(a2[1].x), "f"(a2[1].y));
        asm volatile("red.global.add.v4.f32 [%0], {%1,%2,%3,%4};"
                     :: "l"(dst + 4), "f"(a2[2].x), "f"(a2[2].y),
                        "f"(a2[3].x), "f"(a2[3].y));
        if ((sub & 3) == 0)
            atomicAdd(&g_expsum[curRow * HEADS + (sub >> 2)], es);
    }
}

// ---------------- output projection: (agg/expsum) @ Wo^T + bo ---------------
__global__ void __launch_bounds__(256, 2)
out_gemm(const float* __restrict__ bo,
         float* __restrict__ out, int n) {
    __shared__ __align__(16) __half As[128][AK];
    __shared__ __align__(16) __half Bs[128][AK];
    __shared__ float Inv[128][4];

    int m0 = blockIdx.x * 128;
    int tid = threadIdx.x;
    int wid = tid >> 5, lane = tid & 31;
    int wm = (wid & 3) * 32;
    int wn = (wid >> 2) * 64;

    for (int t = tid; t < 128 * HEADS; t += 256) {
        int ml = t >> 2, hd = t & 3;
        int m = m0 + ml;
        Inv[ml][hd] = (m < n) ? 1.f / (g_expsum[m * HEADS + hd] + 1e-16f) : 0.f;
    }

    float acc[2][8][4];
#pragma unroll
    for (int i = 0; i < 2; i++)
#pragma unroll
        for (int j = 0; j < 8; j++)
#pragma unroll
            for (int t = 0; t < 4; t++) acc[i][j][t] = 0.f;

    __syncthreads();

    for (int k0 = 0; k0 < HID; k0 += 64) {
        for (int idx = tid; idx < 1024; idx += 256) {
            int c = idx >> 3;
            int c16 = idx & 7;
            cp16(smem_u32(&Bs[c][c16 * 8]), &g_woh[c * HID + k0 + c16 * 8]);
        }
        for (int idx = tid; idx < 128 * 16; idx += 256) {
            int r = idx >> 4;
            int k4 = (idx & 15) * 4;
            int m = m0 + r;
            float x[4] = {0.f, 0.f, 0.f, 0.f};
            if (m < n) {
                float4 av = *(const float4*)&g_agg[m * HID + k0 + k4];
                float iv = Inv[r][(k0 + k4) >> 5];
                x[0] = av.x * iv; x[1] = av.y * iv; x[2] = av.z * iv; x[3] = av.w * iv;
            }
            __half2* dst = (__half2*)&As[r][k4];
            dst[0] = __floats2half2_rn(x[0], x[1]);
            dst[1] = __floats2half2_rn(x[2], x[3]);
        }
        cp_commit_wait();
        __syncthreads();

#pragma unroll
        for (int ks = 0; ks < 64; ks += 16) {
            unsigned af[2][4];
#pragma unroll
            for (int mf = 0; mf < 2; mf++) {
                unsigned a = smem_u32(&As[wm + mf * 16 + (lane & 15)][ks + (lane >> 4) * 8]);
                ldsm_x4(af[mf][0], af[mf][1], af[mf][2], af[mf][3], a);
            }
            unsigned bf[8][2];
#pragma unroll
            for (int ng = 0; ng < 4; ng++) {
                unsigned a = smem_u32(&Bs[wn + ng * 16 + (lane & 15)][ks + (lane >> 4) * 8]);
                unsigned r0, r1, r2, r3;
                ldsm_x4(r0, r1, r2, r3, a);
                bf[ng * 2][0] = r0; bf[ng * 2][1] = r2;
                bf[ng * 2 + 1][0] = r1; bf[ng * 2 + 1][1] = r3;
            }
#pragma unroll
            for (int mf = 0; mf < 2; mf++)
#pragma unroll
                for (int nf = 0; nf < 8; nf++)
                    mma16816(acc[mf][nf], af[mf], bf[nf]);
        }
        __syncthreads();
    }

#pragma unroll
    for (int mf = 0; mf < 2; mf++) {
        int r0 = m0 + wm + mf * 16 + (lane >> 2);
#pragma unroll
        for (int nf = 0; nf < 8; nf++) {
            int c = wn + nf * 8 + (lane & 3) * 2;
            float b0 = bo[c], b1 = bo[c + 1];
            if (r0 < n)
                *(float2*)&out[r0 * HID + c] =
                    make_float2(acc[mf][nf][0] + b0, acc[mf][nf][1] + b1);
            if (r0 + 8 < n)
                *(float2*)&out[(r0 + 8) * HID + c] =
                    make_float2(acc[mf][nf][2] + b0, acc[mf][nf][3] + b1);
        }
    }
}

// ---------------- launch ----------------------------------------------------
extern "C" void kernel_launch(void* const* d_in, const int* in_sizes, int n_in,
                              void* d_out, int out_size) {
    const float* h    = (const float*)d_in[0];
    const float* frac = (const float*)d_in[1];
    const float* dist = (const float*)d_in[2];
    const int*   ei   = (const int*)d_in[3];
    const float* We   = (const float*)d_in[4];
    const float* be   = (const float*)d_in[5];
    const float* Wq   = (const float*)d_in[6];
    const float* bq   = (const float*)d_in[7];
    const float* Wk   = (const float*)d_in[8];
    const float* bk   = (const float*)d_in[9];
    const float* Wv   = (const float*)d_in[10];
    const float* bv   = (const float*)d_in[11];
    const float* Wo   = (const float*)d_in[12];
    const float* bo   = (const float*)d_in[13];
    const float* Wg1  = (const float*)d_in[14];
    const float* bg1  = (const float*)d_in[15];
    const float* Wg2  = (const float*)d_in[16];
    const float* bg2  = (const float*)d_in[17];

    int n = in_sizes[0] / HID;
    int E = in_sizes[2];
    float* out = (float*)d_out;

    prep_weights<<<(4 * HID * HID / 4 + 255) / 256, 256>>>(Wq, Wk, Wv, Wo);
    prep_hc<<<(n * 32 + 255) / 256, 256>>>(h, frac, We, be, n);
    zero_cnt<<<(n + 1023) / 1024, 1024>>>(n);
    hist_kernel<<<(E + 511) / 512, 512>>>(ei, E);

    int nch = (n + SCANB - 1) / SCANB;
    scan_phase1<<<nch, SCANB>>>(n);
    scan_phase2<<<1, 32>>>(nch);
    scan_phase3<<<nch, SCANB>>>(n);

    dim3 gA((n + 127) / 128, 3);
    qkv_gemm<<<gA, 256>>>(bq, bk, bv, n);

    scatter_gate<<<(E + 7) / 8, 256>>>(ei, dist, Wg1, bg1, Wg2, bg2, E);

    int warps = (E + 7) / 8;
    edge_csr<<<(warps + 7) / 8, 256>>>(E);

    out_gemm<<<(n + 127) / 128, 256>>>(bo, out, n);
}

// round 17
// speedup vs baseline: 1.4471x; 1.4471x over previous
#include <cuda_runtime.h>
#include <cuda_fp16.h>
#include <math.h>

#define HID   128
#define HEADS 4
#define HDIM  32
#define NMAX  50176
#define EMAX  800000

// ---------------- scratch ---------------------------------------------------
__device__ __half g_hc[NMAX * HID];      // h_combined fp16
__device__ __half g_qh[NMAX * HID];
__device__ __half g_kh[NMAX * HID];
__device__ __half g_vh[NMAX * HID];
__device__ __half g_wqh[HID * HID];      // fp16 weights
__device__ __half g_wkh[HID * HID];
__device__ __half g_wvh[HID * HID];
__device__ __half g_woh[HID * HID];
__device__ float  g_agg[NMAX * HID];     // unnormalized sum of w*v (fp32 atomics)
__device__ float  g_expsum[NMAX * HEADS];

// ---------------- helpers ----------------------------------------------------
__device__ __forceinline__ unsigned smem_u32(const void* p) {
    return (unsigned)__cvta_generic_to_shared(p);
}
__device__ __forceinline__ void cp16(unsigned dst, const void* src) {
    asm volatile("cp.async.cg.shared.global [%0], [%1], 16;" :: "r"(dst), "l"(src));
}
__device__ __forceinline__ void cp_commit_wait() {
    asm volatile("cp.async.commit_group;");
    asm volatile("cp.async.wait_group 0;" ::: "memory");
}
__device__ __forceinline__ void ldsm_x4(unsigned& r0, unsigned& r1,
                                        unsigned& r2, unsigned& r3, unsigned a) {
    asm volatile("ldmatrix.sync.aligned.m8n8.x4.shared.b16 {%0,%1,%2,%3},[%4];"
                 : "=r"(r0), "=r"(r1), "=r"(r2), "=r"(r3) : "r"(a));
}
__device__ __forceinline__ void mma16816(float* c, const unsigned* a, const unsigned* b) {
    asm volatile(
        "mma.sync.aligned.m16n8k16.row.col.f32.f16.f16.f32 "
        "{%0,%1,%2,%3},{%4,%5,%6,%7},{%8,%9},{%0,%1,%2,%3};"
        : "+f"(c[0]), "+f"(c[1]), "+f"(c[2]), "+f"(c[3])
        : "r"(a[0]), "r"(a[1]), "r"(a[2]), "r"(a[3]), "r"(b[0]), "r"(b[1]));
}

#define AK 72   // padded K stride (halves) for smem tiles

// ---------------- prep: h_combined -> fp16, zero agg/expsum, weights fp16 ----
__global__ void prep_all(const float* __restrict__ h,
                         const float* __restrict__ frac,
                         const float* __restrict__ We,
                         const float* __restrict__ be,
                         const float* __restrict__ Wq,
                         const float* __restrict__ Wk,
                         const float* __restrict__ Wv,
                         const float* __restrict__ Wo,
                         int n) {
    int idx = blockIdx.x * blockDim.x + threadIdx.x;
    int nhc = n * 32;
    if (idx < nhc) {
        int m = idx >> 5;
        int k4 = (idx & 31) * 4;
        float4 hv = *(const float4*)&h[m * HID + k4];
        float f0 = __ldg(&frac[m * 3 + 0]);
        float f1 = __ldg(&frac[m * 3 + 1]);
        float f2 = __ldg(&frac[m * 3 + 2]);
        float x[4] = {hv.x, hv.y, hv.z, hv.w};
#pragma unroll
        for (int u = 0; u < 4; u++) {
            int kc = k4 + u;
            x[u] += f0 * __ldg(&We[kc * 3 + 0]) + f1 * __ldg(&We[kc * 3 + 1])
                  + f2 * __ldg(&We[kc * 3 + 2]) + __ldg(&be[kc]);
        }
        __half2* d = (__half2*)&g_hc[m * HID + k4];
        d[0] = __floats2half2_rn(x[0], x[1]);
        d[1] = __floats2half2_rn(x[2], x[3]);
        *(float4*)&g_agg[idx * 4] = make_float4(0.f, 0.f, 0.f, 0.f);
        if (idx < n * HEADS) g_expsum[idx] = 0.f;
    } else {
        int i = idx - nhc;                      // weight conversion: 16384 float4s
        if (i < 4 * HID * HID / 4) {
            int which = i / (HID * HID / 4);
            int off = (i % (HID * HID / 4)) * 4;
            const float* src = (which == 0) ? Wq : (which == 1) ? Wk
                             : (which == 2) ? Wv : Wo;
            __half* dst = (which == 0) ? g_wqh : (which == 1) ? g_wkh
                        : (which == 2) ? g_wvh : g_woh;
            float4 v = *(const float4*)&src[off];
            __half2* d = (__half2*)&dst[off];
            d[0] = __floats2half2_rn(v.x, v.y);
            d[1] = __floats2half2_rn(v.z, v.w);
        }
    }
}

// ---------------- QKV projections: pure fp16 GEMM w/ cp.async tiles ----------
__global__ void __launch_bounds__(256, 2)
qkv_gemm(const float* __restrict__ bq,
         const float* __restrict__ bk,
         const float* __restrict__ bv,
         int n) {
    __shared__ __align__(16) __half As[128][AK];
    __shared__ __align__(16) __half Bs[128][AK];

    int m0 = blockIdx.x * 128;
    const __half* W; const float* bias; __half* outbuf;
    if (blockIdx.y == 0)      { W = g_wqh; bias = bq; outbuf = g_qh; }
    else if (blockIdx.y == 1) { W = g_wkh; bias = bk; outbuf = g_kh; }
    else                      { W = g_wvh; bias = bv; outbuf = g_vh; }

    int tid = threadIdx.x;
    int wid = tid >> 5, lane = tid & 31;
    int wm = (wid & 3) * 32;
    int wn = (wid >> 2) * 64;

    float acc[2][8][4];
#pragma unroll
    for (int i = 0; i < 2; i++)
#pragma unroll
        for (int j = 0; j < 8; j++)
#pragma unroll
            for (int t = 0; t < 4; t++) acc[i][j][t] = 0.f;

    for (int k0 = 0; k0 < HID; k0 += 64) {
        for (int idx = tid; idx < 1024; idx += 256) {
            int r = idx >> 3;
            int c16 = idx & 7;
            cp16(smem_u32(&As[r][c16 * 8]), &g_hc[(m0 + r) * HID + k0 + c16 * 8]);
        }
        for (int idx = tid; idx < 1024; idx += 256) {
            int c = idx >> 3;
            int c16 = idx & 7;
            cp16(smem_u32(&Bs[c][c16 * 8]), &W[c * HID + k0 + c16 * 8]);
        }
        cp_commit_wait();
        __syncthreads();

#pragma unroll
        for (int ks = 0; ks < 64; ks += 16) {
            unsigned af[2][4];
#pragma unroll
            for (int mf = 0; mf < 2; mf++) {
                unsigned a = smem_u32(&As[wm + mf * 16 + (lane & 15)][ks + (lane >> 4) * 8]);
                ldsm_x4(af[mf][0], af[mf][1], af[mf][2], af[mf][3], a);
            }
            unsigned bf[8][2];
#pragma unroll
            for (int ng = 0; ng < 4; ng++) {
                unsigned a = smem_u32(&Bs[wn + ng * 16 + (lane & 15)][ks + (lane >> 4) * 8]);
                unsigned r0, r1, r2, r3;
                ldsm_x4(r0, r1, r2, r3, a);
                bf[ng * 2][0] = r0; bf[ng * 2][1] = r2;
                bf[ng * 2 + 1][0] = r1; bf[ng * 2 + 1][1] = r3;
            }
#pragma unroll
            for (int mf = 0; mf < 2; mf++)
#pragma unroll
                for (int nf = 0; nf < 8; nf++)
                    mma16816(acc[mf][nf], af[mf], bf[nf]);
        }
        __syncthreads();
    }

#pragma unroll
    for (int mf = 0; mf < 2; mf++) {
        int r0 = m0 + wm + mf * 16 + (lane >> 2);
#pragma unroll
        for (int nf = 0; nf < 8; nf++) {
            int c = wn + nf * 8 + (lane & 3) * 2;
            float b0 = bias[c], b1 = bias[c + 1];
            if (r0 < n)
                *(__half2*)&outbuf[r0 * HID + c] =
                    __floats2half2_rn(acc[mf][nf][0] + b0, acc[mf][nf][1] + b1);
            if (r0 + 8 < n)
                *(__half2*)&outbuf[(r0 + 8) * HID + c] =
                    __floats2half2_rn(acc[mf][nf][2] + b0, acc[mf][nf][3] + b1);
        }
    }
}

// ---------------- fused per-edge: TWO edges per warp (16 lanes each) --------
// half = lane>>4 selects edge; sub = lane&15 covers 16B of the row.
// head = sub>>2 (4 lanes per head). Gate MLP: 2 hidden units per lane.
// expsum updated with a single red.v4 per edge (per-head w gathered via shfl).
__global__ void edge_fused2(const int* __restrict__ ei,
                            const float* __restrict__ dist,
                            const float* __restrict__ Wg1, const float* __restrict__ bg1,
                            const float* __restrict__ Wg2, const float* __restrict__ bg2,
                            int E) {
    int warp = (blockIdx.x * blockDim.x + threadIdx.x) >> 5;
    int lane = threadIdx.x & 31;
    int e0 = warp * 2;
    if (e0 >= E) return;
    int half = lane >> 4;
    int sub  = lane & 15;
    int edge = e0 + half;
    bool valid = edge < E;
    int esafe = valid ? edge : e0;

    int row = __ldg(&ei[esafe]);
    int col = __ldg(&ei[E + esafe]);

    union { float4 f; __half2 h[4]; } q4, k4, v4;
    q4.f = *(const float4*)&g_qh[row * HID + sub * 8];
    k4.f = *(const float4*)&g_kh[col * HID + sub * 8];
    v4.f = *(const float4*)&g_vh[col * HID + sub * 8];

    float p = 0.f;
#pragma unroll
    for (int u = 0; u < 4; u++) {
        float2 qq = __half22float2(q4.h[u]);
        float2 kk = __half22float2(k4.h[u]);
        p += qq.x * kk.x + qq.y * kk.y;
    }
    // reduce over the 4 lanes of this head group
    p += __shfl_xor_sync(0xFFFFFFFFu, p, 1);
    p += __shfl_xor_sync(0xFFFFFFFFu, p, 2);

    // gate MLP: 1 -> 32 (silu) -> 1 (sigmoid); 2 hidden units per lane
    float d = __ldg(&dist[esafe]);
    int u0 = sub * 2;
    float t0 = fmaf(d, Wg1[u0], bg1[u0]);
    float t1 = fmaf(d, Wg1[u0 + 1], bg1[u0 + 1]);
    float gp = (t0 / (1.f + __expf(-t0))) * Wg2[u0]
             + (t1 / (1.f + __expf(-t1))) * Wg2[u0 + 1];
    gp += __shfl_xor_sync(0xFFFFFFFFu, gp, 8);
    gp += __shfl_xor_sync(0xFFFFFFFFu, gp, 4);
    gp += __shfl_xor_sync(0xFFFFFFFFu, gp, 2);
    gp += __shfl_xor_sync(0xFFFFFFFFu, gp, 1);
    float g = 1.f / (1.f + __expf(-(gp + bg2[0])));

    float w = __expf(p * 0.17677669529663687f * g);   // 1/sqrt(32)

    // gather the 4 per-head w values of this half (convergent shfls)
    int hb = lane & 16;
    float w0 = __shfl_sync(0xFFFFFFFFu, w, hb + 0);
    float w1 = __shfl_sync(0xFFFFFFFFu, w, hb + 4);
    float w2 = __shfl_sync(0xFFFFFFFFu, w, hb + 8);
    float w3 = __shfl_sync(0xFFFFFFFFu, w, hb + 12);

    if (valid) {
        float* dst = &g_agg[row * HID + sub * 8];
        float2 v0 = __half22float2(v4.h[0]), v1 = __half22float2(v4.h[1]);
        float2 v2 = __half22float2(v4.h[2]), v3 = __half22float2(v4.h[3]);
        asm volatile("red.global.add.v4.f32 [%0], {%1,%2,%3,%4};"
                     :: "l"(dst), "f"(w * v0.x), "f"(w * v0.y),
                        "f"(w * v1.x), "f"(w * v1.y));
        asm volatile("red.global.add.v4.f32 [%0], {%1,%2,%3,%4};"
                     :: "l"(dst + 4), "f"(w * v2.x), "f"(w * v2.y),
                        "f"(w * v3.x), "f"(w * v3.y));
        if (sub == 0)
            asm volatile("red.global.add.v4.f32 [%0], {%1,%2,%3,%4};"
                         :: "l"(&g_expsum[row * HEADS]),
                            "f"(w0), "f"(w1), "f"(w2), "f"(w3));
    }
}

// ---------------- output projection: (agg/expsum) @ Wo^T + bo ---------------
__global__ void __launch_bounds__(256, 2)
out_gemm(const float* __restrict__ bo,
         float* __restrict__ out, int n) {
    __shared__ __align__(16) __half As[128][AK];
    __shared__ __align__(16) __half Bs[128][AK];
    __shared__ float Inv[128][4];

    int m0 = blockIdx.x * 128;
    int tid = threadIdx.x;
    int wid = tid >> 5, lane = tid & 31;
    int wm = (wid & 3) * 32;
    int wn = (wid >> 2) * 64;

    for (int t = tid; t < 128 * HEADS; t += 256) {
        int ml = t >> 2, hd = t & 3;
        int m = m0 + ml;
        Inv[ml][hd] = (m < n) ? 1.f / (g_expsum[m * HEADS + hd] + 1e-16f) : 0.f;
    }

    float acc[2][8][4];
#pragma unroll
    for (int i = 0; i < 2; i++)
#pragma unroll
        for (int j = 0; j < 8; j++)
#pragma unroll
            for (int t = 0; t < 4; t++) acc[i][j][t] = 0.f;

    __syncthreads();

    for (int k0 = 0; k0 < HID; k0 += 64) {
        for (int idx = tid; idx < 1024; idx += 256) {
            int c = idx >> 3;
            int c16 = idx & 7;
            cp16(smem_u32(&Bs[c][c16 * 8]), &g_woh[c * HID + k0 + c16 * 8]);
        }
        for (int idx = tid; idx < 128 * 16; idx += 256) {
            int r = idx >> 4;
            int k4 = (idx & 15) * 4;
            int m = m0 + r;
            float x[4] = {0.f, 0.f, 0.f, 0.f};
            if (m < n) {
                float4 av = *(const float4*)&g_agg[m * HID + k0 + k4];
                float iv = Inv[r][(k0 + k4) >> 5];
                x[0] = av.x * iv; x[1] = av.y * iv; x[2] = av.z * iv; x[3] = av.w * iv;
            }
            __half2* dst = (__half2*)&As[r][k4];
            dst[0] = __floats2half2_rn(x[0], x[1]);
            dst[1] = __floats2half2_rn(x[2], x[3]);
        }
        cp_commit_wait();
        __syncthreads();

#pragma unroll
        for (int ks = 0; ks < 64; ks += 16) {
            unsigned af[2][4];
#pragma unroll
            for (int mf = 0; mf < 2; mf++) {
                unsigned a = smem_u32(&As[wm + mf * 16 + (lane & 15)][ks + (lane >> 4) * 8]);
                ldsm_x4(af[mf][0], af[mf][1], af[mf][2], af[mf][3], a);
            }
            unsigned bf[8][2];
#pragma unroll
            for (int ng = 0; ng < 4; ng++) {
                unsigned a = smem_u32(&Bs[wn + ng * 16 + (lane & 15)][ks + (lane >> 4) * 8]);
                unsigned r0, r1, r2, r3;
                ldsm_x4(r0, r1, r2, r3, a);
                bf[ng * 2][0] = r0; bf[ng * 2][1] = r2;
                bf[ng * 2 + 1][0] = r1; bf[ng * 2 + 1][1] = r3;
            }
#pragma unroll
            for (int mf = 0; mf < 2; mf++)
#pragma unroll
                for (int nf = 0; nf < 8; nf++)
                    mma16816(acc[mf][nf], af[mf], bf[nf]);
        }
        __syncthreads();
    }

#pragma unroll
    for (int mf = 0; mf < 2; mf++) {
        int r0 = m0 + wm + mf * 16 + (lane >> 2);
#pragma unroll
        for (int nf = 0; nf < 8; nf++) {
            int c = wn + nf * 8 + (lane & 3) * 2;
            float b0 = bo[c], b1 = bo[c + 1];
            if (r0 < n)
                *(float2*)&out[r0 * HID + c] =
                    make_float2(acc[mf][nf][0] + b0, acc[mf][nf][1] + b1);
            if (r0 + 8 < n)
                *(float2*)&out[(r0 + 8) * HID + c] =
                    make_float2(acc[mf][nf][2] + b0, acc[mf][nf][3] + b1);
        }
    }
}

// ---------------- launch ----------------------------------------------------
extern "C" void kernel_launch(void* const* d_in, const int* in_sizes, int n_in,
                              void* d_out, int out_size) {
    const float* h    = (const float*)d_in[0];
    const float* frac = (const float*)d_in[1];
    const float* dist = (const float*)d_in[2];
    const int*   ei   = (const int*)d_in[3];
    const float* We   = (const float*)d_in[4];
    const float* be   = (const float*)d_in[5];
    const float* Wq   = (const float*)d_in[6];
    const float* bq   = (const float*)d_in[7];
    const float* Wk   = (const float*)d_in[8];
    const float* bk   = (const float*)d_in[9];
    const float* Wv   = (const float*)d_in[10];
    const float* bv   = (const float*)d_in[11];
    const float* Wo   = (const float*)d_in[12];
    const float* bo   = (const float*)d_in[13];
    const float* Wg1  = (const float*)d_in[14];
    const float* bg1  = (const float*)d_in[15];
    const float* Wg2  = (const float*)d_in[16];
    const float* bg2  = (const float*)d_in[17];

    int n = in_sizes[0] / HID;
    int E = in_sizes[2];
    float* out = (float*)d_out;

    int prep_items = n * 32 + 4 * HID * HID / 4;
    prep_all<<<(prep_items + 255) / 256, 256>>>(h, frac, We, be, Wq, Wk, Wv, Wo, n);

    dim3 gA((n + 127) / 128, 3);
    qkv_gemm<<<gA, 256>>>(bq, bk, bv, n);

    int warps = (E + 1) / 2;
    edge_fused2<<<(warps + 7) / 8, 256>>>(ei, dist, Wg1, bg1, Wg2, bg2, E);

    out_gemm<<<(n + 127) / 128, 256>>>(bo, out, n);
}